// round 4
// baseline (speedup 1.0000x reference)
#include <cuda_runtime.h>
#include <cuda_bf16.h>

#define NDOF 7
#define GRAV 9.81f
#define TPB 128
#define EPB (2*TPB)              // elements per block (256)
#define FLB (EPB*NDOF)           // floats per input array per block (1792)
#define STR 258                  // padded row stride (floats) per dof row

typedef unsigned long long u64;

// ---------------- packed f32x2 primitives ----------------
__device__ __forceinline__ u64 f2pack(float lo, float hi) {
    u64 r; asm("mov.b64 %0,{%1,%2};" : "=l"(r) : "f"(lo), "f"(hi)); return r;
}
__device__ __forceinline__ void f2unpack(u64 a, float& lo, float& hi) {
    asm("mov.b64 {%0,%1},%2;" : "=f"(lo), "=f"(hi) : "l"(a));
}
__device__ __forceinline__ u64 f2add(u64 a, u64 b) {
    u64 r; asm("add.rn.f32x2 %0,%1,%2;" : "=l"(r) : "l"(a), "l"(b)); return r;
}
__device__ __forceinline__ u64 f2mul(u64 a, u64 b) {
    u64 r; asm("mul.rn.f32x2 %0,%1,%2;" : "=l"(r) : "l"(a), "l"(b)); return r;
}
__device__ __forceinline__ u64 f2fma(u64 a, u64 b, u64 c) {
    u64 r; asm("fma.rn.f32x2 %0,%1,%2,%3;" : "=l"(r) : "l"(a), "l"(b), "l"(c)); return r;
}
__device__ __forceinline__ u64 f2neg(u64 a) { return a ^ 0x8000000080000000ULL; }

__device__ __forceinline__ void rtmv2(const u64 R[9], const u64 v[3], u64 o[3]) {
    o[0] = f2fma(R[6], v[2], f2fma(R[3], v[1], f2mul(R[0], v[0])));
    o[1] = f2fma(R[7], v[2], f2fma(R[4], v[1], f2mul(R[1], v[0])));
    o[2] = f2fma(R[8], v[2], f2fma(R[5], v[1], f2mul(R[2], v[0])));
}
__device__ __forceinline__ void rmv2(const u64 R[9], const u64 v[3], u64 o[3]) {
    o[0] = f2fma(R[2], v[2], f2fma(R[1], v[1], f2mul(R[0], v[0])));
    o[1] = f2fma(R[5], v[2], f2fma(R[4], v[1], f2mul(R[3], v[0])));
    o[2] = f2fma(R[8], v[2], f2fma(R[7], v[1], f2mul(R[6], v[0])));
}
__device__ __forceinline__ void cross2v(const u64 a[3], const u64 b[3], u64 o[3]) {
    o[0] = f2fma(a[1], b[2], f2neg(f2mul(a[2], b[1])));
    o[1] = f2fma(a[2], b[0], f2neg(f2mul(a[0], b[2])));
    o[2] = f2fma(a[0], b[1], f2neg(f2mul(a[1], b[0])));
}

// ---------------- packed joint parameters ----------------
struct JP2 {
    u64 C0[9], C1[9], C2[9];   // R = C0 + s*C1 - c*C2 (each half duplicated)
    u64 u0[3], u1[3], u2[3];   // u_k = C_k^T p
    u64 p[3], ax[3], mc[3];
    u64 Io[9];
    u64 m, damping;
};

__device__ JP2 g_stage2[NDOF];
__constant__ JP2 c_par2[NDOF];

__device__ __forceinline__ u64 dup(float x) {
    unsigned u = __float_as_uint(x);
    return ((u64)u << 32) | u;
}

__device__ __forceinline__ void mat3mul(const float* A, const float* B, float* C) {
#pragma unroll
    for (int i = 0; i < 3; i++)
#pragma unroll
        for (int j = 0; j < 3; j++)
            C[i*3+j] = A[i*3+0]*B[0*3+j] + A[i*3+1]*B[1*3+j] + A[i*3+2]*B[2*3+j];
}

__global__ void prep_kernel(const float* __restrict__ rot_fix,
                            const float* __restrict__ trans_fix,
                            const float* __restrict__ joint_axes,
                            const float* __restrict__ mass,
                            const float* __restrict__ com,
                            const float* __restrict__ inertia,
                            const float* __restrict__ damping) {
    int d = threadIdx.x;
    if (d >= NDOF) return;
    float a0 = joint_axes[3*d+0], a1 = joint_axes[3*d+1], a2 = joint_axes[3*d+2];
    float K[9]  = {0.f, -a2, a1,   a2, 0.f, -a0,   -a1, a0, 0.f};
    float K2[9];
    mat3mul(K, K, K2);
    const float* M0 = rot_fix + (d+1)*9;
    float M1[9], M2[9];
    mat3mul(M0, K, M1);
    mat3mul(M0, K2, M2);
    float C0[9], C1[9], C2[9];
#pragma unroll
    for (int k = 0; k < 9; k++) {
        C0[k] = M0[k] + M2[k];
        C1[k] = M1[k];
        C2[k] = M2[k];
        g_stage2[d].C0[k] = dup(C0[k]);
        g_stage2[d].C1[k] = dup(C1[k]);
        g_stage2[d].C2[k] = dup(C2[k]);
    }
    float p0 = trans_fix[(d+1)*3+0], p1 = trans_fix[(d+1)*3+1], p2 = trans_fix[(d+1)*3+2];
    g_stage2[d].p[0] = dup(p0); g_stage2[d].p[1] = dup(p1); g_stage2[d].p[2] = dup(p2);
#pragma unroll
    for (int j = 0; j < 3; j++) {
        g_stage2[d].u0[j] = dup(C0[0*3+j]*p0 + C0[1*3+j]*p1 + C0[2*3+j]*p2);
        g_stage2[d].u1[j] = dup(C1[0*3+j]*p0 + C1[1*3+j]*p1 + C1[2*3+j]*p2);
        g_stage2[d].u2[j] = dup(C2[0*3+j]*p0 + C2[1*3+j]*p1 + C2[2*3+j]*p2);
    }
    g_stage2[d].ax[0] = dup(a0); g_stage2[d].ax[1] = dup(a1); g_stage2[d].ax[2] = dup(a2);
    float m = mass[d+1];
    g_stage2[d].m = dup(m);
    float c0 = com[(d+1)*3+0], c1 = com[(d+1)*3+1], c2 = com[(d+1)*3+2];
    g_stage2[d].mc[0] = dup(m*c0); g_stage2[d].mc[1] = dup(m*c1); g_stage2[d].mc[2] = dup(m*c2);
    float cc = c0*c0 + c1*c1 + c2*c2;
    float cv[3] = {c0, c1, c2};
#pragma unroll
    for (int i = 0; i < 3; i++)
#pragma unroll
        for (int j = 0; j < 3; j++)
            g_stage2[d].Io[i*3+j] = dup(inertia[(d+1)*9 + i*3 + j] +
                                        m * ((i == j ? cc : 0.f) - cv[i]*cv[j]));
    g_stage2[d].damping = dup(damping[d]);
}

// ---------------- main packed kernel ----------------
// smem: 3 input arrays [NDOF][STR] floats + fl scan buffer 21*TPB u64
//   3*7*258*4 = 21672 B  +  21*128*8 = 21504 B  => 43176 B  (< 48 KB, no attr needed)
__global__ void __launch_bounds__(TPB, 3)
rnea_kernel(const float* __restrict__ q,
            const float* __restrict__ qd,
            const float* __restrict__ qdd,
            float* __restrict__ out, int B) {
    __shared__ float sq[NDOF*STR];
    __shared__ float sqd[NDOF*STR];
    __shared__ float sqdd[NDOF*STR];
    __shared__ u64 sfl[21*TPB];

    const int t = threadIdx.x;
    const long base = (long)blockIdx.x * FLB;
    const long total = (long)B * NDOF;

    // coalesced load, scatter to [dof][elem] layout (padded stride STR)
#pragma unroll
    for (int i = 0; i < 2*NDOF; i++) {
        int gl = i * TPB + t;           // 0 .. FLB-1
        long g = base + gl;
        float a = 0.f, bb = 0.f, c = 0.f;
        if (g < total) { a = q[g]; bb = qd[g]; c = qdd[g]; }
        int elem = gl / NDOF;
        int dof  = gl - NDOF * elem;
        int idx = dof * STR + elem;
        sq[idx] = a; sqd[idx] = bb; sqdd[idx] = c;
    }
    __syncthreads();

    const int e2 = 2 * t;               // this thread's element pair base

    u64 fa[NDOF][3];

    u64 vl[3] = {0,0,0};
    u64 va[3] = {0,0,0};
    u64 al[3] = {0,0,dup(GRAV)};
    u64 aa[3] = {0,0,0};

#pragma unroll
    for (int d = 0; d < NDOF; d++) {
        const JP2& P = c_par2[d];
        u64 qq   = *(const u64*)&sq  [d*STR + e2];
        u64 qdv  = *(const u64*)&sqd [d*STR + e2];
        u64 qddv = *(const u64*)&sqdd[d*STR + e2];

        float q0, q1, s0, c0s, s1, c1s;
        f2unpack(qq, q0, q1);
        __sincosf(q0, &s0, &c0s);
        __sincosf(q1, &s1, &c1s);
        u64 si  = f2pack(s0, s1);
        u64 nci = f2neg(f2pack(c0s, c1s));

        u64 R[9];
#pragma unroll
        for (int k = 0; k < 9; k++)
            R[k] = f2fma(si, P.C1[k], f2fma(nci, P.C2[k], P.C0[k]));

        u64 pinv[3];
#pragma unroll
        for (int j = 0; j < 3; j++)
            pinv[j] = f2neg(f2fma(si, P.u1[j], f2fma(nci, P.u2[j], P.u0[j])));

        u64 va_n[3], tv[3], cx[3];
        rtmv2(R, va, va_n);
        rtmv2(R, vl, tv);
        cross2v(pinv, va_n, cx);
#pragma unroll
        for (int j = 0; j < 3; j++) vl[j] = f2add(tv[j], cx[j]);

        u64 jv[3];
#pragma unroll
        for (int j = 0; j < 3; j++) jv[j] = f2mul(qdv, P.ax[j]);
#pragma unroll
        for (int j = 0; j < 3; j++) va[j] = f2add(va_n[j], jv[j]);

        u64 aa_n[3], al_n[3];
        rtmv2(R, aa, aa_n);
        rtmv2(R, al, tv);
        cross2v(pinv, aa_n, cx);
#pragma unroll
        for (int j = 0; j < 3; j++) al_n[j] = f2add(tv[j], cx[j]);

        cross2v(va, jv, cx);
#pragma unroll
        for (int j = 0; j < 3; j++)
            aa[j] = f2add(f2fma(qddv, P.ax[j], aa_n[j]), cx[j]);

        cross2v(vl, jv, cx);
#pragma unroll
        for (int j = 0; j < 3; j++) al[j] = f2add(al_n[j], cx[j]);

        // inertial wrench
        u64 Ial[3], Iaa[3], Ivl[3], Iva[3];
        cross2v(aa, P.mc, cx);
#pragma unroll
        for (int j = 0; j < 3; j++) Ial[j] = f2fma(P.m, al[j], cx[j]);
        rmv2(P.Io, aa, tv);
        cross2v(P.mc, al, cx);
#pragma unroll
        for (int j = 0; j < 3; j++) Iaa[j] = f2add(tv[j], cx[j]);

        cross2v(va, P.mc, cx);
#pragma unroll
        for (int j = 0; j < 3; j++) Ivl[j] = f2fma(P.m, vl[j], cx[j]);
        rmv2(P.Io, va, tv);
        cross2v(P.mc, vl, cx);
#pragma unroll
        for (int j = 0; j < 3; j++) Iva[j] = f2add(tv[j], cx[j]);

        cross2v(va, Ivl, cx);
#pragma unroll
        for (int j = 0; j < 3; j++)
            sfl[(d*3+j)*TPB + t] = f2add(Ial[j], cx[j]);

        u64 cx2[3];
        cross2v(va, Iva, cx);
        cross2v(vl, Ivl, cx2);
#pragma unroll
        for (int j = 0; j < 3; j++)
            fa[d][j] = f2add(Iaa[j], f2add(cx[j], cx2[j]));
    }

    // ---------------- backward scan ----------------
    u64 cl[3] = {0,0,0};
    u64 ca[3] = {0,0,0};
#pragma unroll
    for (int d = NDOF - 1; d >= 0; d--) {
        const JP2& P = c_par2[d];
        u64 qq  = *(const u64*)&sq [d*STR + e2];
        u64 qdv = *(const u64*)&sqd[d*STR + e2];

        float q0, q1, s0, c0s, s1, c1s;
        f2unpack(qq, q0, q1);
        __sincosf(q0, &s0, &c0s);
        __sincosf(q1, &s1, &c1s);
        u64 si  = f2pack(s0, s1);
        u64 nci = f2neg(f2pack(c0s, c1s));

        u64 R[9];
#pragma unroll
        for (int k = 0; k < 9; k++)
            R[k] = f2fma(si, P.C1[k], f2fma(nci, P.C2[k], P.C0[k]));

        u64 tl[3], ta[3];
#pragma unroll
        for (int j = 0; j < 3; j++) {
            tl[j] = f2add(sfl[(d*3+j)*TPB + t], cl[j]);
            ta[j] = f2add(fa[d][j], ca[j]);
        }

        u64 tau = f2fma(ta[2], P.ax[2],
                  f2fma(ta[1], P.ax[1],
                  f2mul(ta[0], P.ax[0])));
        tau = f2fma(P.damping, qdv, tau);

        u64 nl[3], tv[3], cx[3];
        rmv2(R, tl, nl);
        rmv2(R, ta, tv);
        cross2v(P.p, nl, cx);
#pragma unroll
        for (int j = 0; j < 3; j++) {
            cl[j] = nl[j];
            ca[j] = f2add(tv[j], cx[j]);
        }

        *(u64*)&sqdd[d*STR + e2] = tau;   // own slots; reused as output staging
    }

    __syncthreads();
    // gather from [dof][elem] layout, coalesced store
#pragma unroll
    for (int i = 0; i < 2*NDOF; i++) {
        int gl = i * TPB + t;
        long g = base + gl;
        int elem = gl / NDOF;
        int dof  = gl - NDOF * elem;
        if (g < total) out[g] = sqdd[dof * STR + elem];
    }
}

extern "C" void kernel_launch(void* const* d_in, const int* in_sizes, int n_in,
                              void* d_out, int out_size) {
    const float* q          = (const float*)d_in[0];
    const float* qd         = (const float*)d_in[1];
    const float* qdd_des    = (const float*)d_in[2];
    const float* rot_fix    = (const float*)d_in[3];
    const float* trans_fix  = (const float*)d_in[4];
    const float* joint_axes = (const float*)d_in[5];
    const float* mass       = (const float*)d_in[6];
    const float* com        = (const float*)d_in[7];
    const float* inertia    = (const float*)d_in[8];
    const float* damping    = (const float*)d_in[9];
    float* out = (float*)d_out;

    int B = in_sizes[0] / NDOF;

    prep_kernel<<<1, 32>>>(rot_fix, trans_fix, joint_axes, mass, com, inertia, damping);

    void* src = nullptr;
    cudaGetSymbolAddress(&src, g_stage2);
    cudaMemcpyToSymbolAsync(c_par2, src, sizeof(JP2) * NDOF, 0,
                            cudaMemcpyDeviceToDevice, 0);

    int blocks = (B + EPB - 1) / EPB;
    rnea_kernel<<<blocks, TPB>>>(q, qd, qdd_des, out, B);
}

// round 6
// speedup vs baseline: 1.4806x; 1.4806x over previous
#include <cuda_runtime.h>
#include <cuda_bf16.h>

#define NDOF 7
#define GRAV 9.81f
#define TPB 128

struct JP {
    float Rf[9];   // rot_fix[d+1] row-major
    float u[3];    // Rfix^T p
    float p[3];    // trans_fix[d+1]
    float mc[3];   // m*com
    float Io[9];   // inertia + m*(|c|^2 I - c c^T)
    float m;
    float damping;
};

__device__ JP g_stage[NDOF];
__constant__ JP c_par[NDOF];

__global__ void prep_kernel(const float* __restrict__ rot_fix,
                            const float* __restrict__ trans_fix,
                            const float* __restrict__ mass,
                            const float* __restrict__ com,
                            const float* __restrict__ inertia,
                            const float* __restrict__ damping) {
    int d = threadIdx.x;
    if (d >= NDOF) return;
    JP P;
#pragma unroll
    for (int k = 0; k < 9; k++) P.Rf[k] = rot_fix[(d+1)*9 + k];
    float p0 = trans_fix[(d+1)*3+0], p1 = trans_fix[(d+1)*3+1], p2 = trans_fix[(d+1)*3+2];
    P.p[0] = p0; P.p[1] = p1; P.p[2] = p2;
#pragma unroll
    for (int j = 0; j < 3; j++)
        P.u[j] = P.Rf[0*3+j]*p0 + P.Rf[1*3+j]*p1 + P.Rf[2*3+j]*p2;
    float m = mass[d+1];
    P.m = m;
    float c0 = com[(d+1)*3+0], c1 = com[(d+1)*3+1], c2 = com[(d+1)*3+2];
    P.mc[0] = m*c0; P.mc[1] = m*c1; P.mc[2] = m*c2;
    float cc = c0*c0 + c1*c1 + c2*c2;
    float cv[3] = {c0, c1, c2};
#pragma unroll
    for (int i = 0; i < 3; i++)
#pragma unroll
        for (int j = 0; j < 3; j++)
            P.Io[i*3+j] = inertia[(d+1)*9 + i*3 + j] + m * ((i == j ? cc : 0.f) - cv[i]*cv[j]);
    P.damping = damping[d];
    g_stage[d] = P;
}

// o = M^T v   (M row-major 3x3)
__device__ __forceinline__ void mtv(const float M[9], const float v[3], float o[3]) {
    o[0] = M[0]*v[0] + M[3]*v[1] + M[6]*v[2];
    o[1] = M[1]*v[0] + M[4]*v[1] + M[7]*v[2];
    o[2] = M[2]*v[0] + M[5]*v[1] + M[8]*v[2];
}
// o = M v
__device__ __forceinline__ void mv(const float M[9], const float v[3], float o[3]) {
    o[0] = M[0]*v[0] + M[1]*v[1] + M[2]*v[2];
    o[1] = M[3]*v[0] + M[4]*v[1] + M[5]*v[2];
    o[2] = M[6]*v[0] + M[7]*v[1] + M[8]*v[2];
}
__device__ __forceinline__ void cross3(const float a[3], const float b[3], float o[3]) {
    o[0] = a[1]*b[2] - a[2]*b[1];
    o[1] = a[2]*b[0] - a[0]*b[2];
    o[2] = a[0]*b[1] - a[1]*b[0];
}
// Rot_K(angle)^T v (K: 2=z, 1=y); s includes the axis sign.
template<int K>
__device__ __forceinline__ void rotT(float s, float c, const float v[3], float o[3]) {
    if (K == 2) { o[0] = c*v[0] + s*v[1]; o[1] = c*v[1] - s*v[0]; o[2] = v[2]; }
    else        { o[0] = c*v[0] - s*v[2]; o[1] = v[1];            o[2] = c*v[2] + s*v[0]; }
}
// Rot_K(angle) v
template<int K>
__device__ __forceinline__ void rotF(float s, float c, const float v[3], float o[3]) {
    if (K == 2) { o[0] = c*v[0] - s*v[1]; o[1] = s*v[0] + c*v[1]; o[2] = v[2]; }
    else        { o[0] = c*v[0] + s*v[2]; o[1] = v[1];            o[2] = c*v[2] - s*v[0]; }
}

template<int K, bool NEG>
__device__ __forceinline__ void fwd_step(
    const JP& P, float qv, float qdv, float qddv,
    float vl[3], float va[3], float al[3], float aa[3],
    float fld[3], float fad[3])
{
    float si, ci;
    __sincosf(qv, &si, &ci);
    float s  = NEG ? -si   : si;
    float w  = NEG ? -qdv  : qdv;
    float wd = NEG ? -qddv : qddv;

    float h[3], va_n[3], vl_n[3], aa_n[3], al_n[3], pinv[3], cx[3];
    mtv(P.Rf, va, h);  rotT<K>(s, ci, h, va_n);
    mtv(P.Rf, vl, h);  rotT<K>(s, ci, h, vl_n);
    mtv(P.Rf, aa, h);  rotT<K>(s, ci, h, aa_n);
    mtv(P.Rf, al, h);  rotT<K>(s, ci, h, al_n);
    rotT<K>(s, ci, P.u, pinv);
    pinv[0] = -pinv[0]; pinv[1] = -pinv[1]; pinv[2] = -pinv[2];

    cross3(pinv, va_n, cx);
    vl[0] = vl_n[0] + cx[0]; vl[1] = vl_n[1] + cx[1]; vl[2] = vl_n[2] + cx[2];

    va[0] = va_n[0]; va[1] = va_n[1]; va[2] = va_n[2];
    if (K == 2) va[2] += w; else va[1] += w;

    cross3(pinv, aa_n, cx);
    al_n[0] += cx[0]; al_n[1] += cx[1]; al_n[2] += cx[2];

    // aa = aa_n + wd*e_K + w*cross(va, e_K)
    aa[0] = aa_n[0]; aa[1] = aa_n[1]; aa[2] = aa_n[2];
    if (K == 2) {
        aa[2] += wd;
        aa[0] += w*va[1]; aa[1] -= w*va[0];
    } else {
        aa[1] += wd;
        aa[0] -= w*va[2]; aa[2] += w*va[0];
    }

    // al = al_n + w*cross(vl, e_K)
    al[0] = al_n[0]; al[1] = al_n[1]; al[2] = al_n[2];
    if (K == 2) { al[0] += w*vl[1]; al[1] -= w*vl[0]; }
    else        { al[0] -= w*vl[2]; al[2] += w*vl[0]; }

    // inertial wrench
    float Ial[3], Iaa[3], Ivl[3], Iva[3], tv[3];
    cross3(aa, P.mc, cx);
    Ial[0] = P.m*al[0] + cx[0]; Ial[1] = P.m*al[1] + cx[1]; Ial[2] = P.m*al[2] + cx[2];
    mv(P.Io, aa, tv);
    cross3(P.mc, al, cx);
    Iaa[0] = tv[0] + cx[0]; Iaa[1] = tv[1] + cx[1]; Iaa[2] = tv[2] + cx[2];

    cross3(va, P.mc, cx);
    Ivl[0] = P.m*vl[0] + cx[0]; Ivl[1] = P.m*vl[1] + cx[1]; Ivl[2] = P.m*vl[2] + cx[2];
    mv(P.Io, va, tv);
    cross3(P.mc, vl, cx);
    Iva[0] = tv[0] + cx[0]; Iva[1] = tv[1] + cx[1]; Iva[2] = tv[2] + cx[2];

    cross3(va, Ivl, cx);
    fld[0] = Ial[0] + cx[0]; fld[1] = Ial[1] + cx[1]; fld[2] = Ial[2] + cx[2];
    float cx2[3];
    cross3(va, Iva, cx);
    cross3(vl, Ivl, cx2);
    fad[0] = Iaa[0] + cx[0] + cx2[0];
    fad[1] = Iaa[1] + cx[1] + cx2[1];
    fad[2] = Iaa[2] + cx[2] + cx2[2];
}

template<int K, bool NEG>
__device__ __forceinline__ float bwd_step(
    const JP& P, float qv, float qdv,
    const float fld[3], const float fad[3],
    float cl[3], float ca[3])
{
    float si, ci;
    __sincosf(qv, &si, &ci);
    float s = NEG ? -si : si;

    float tl[3] = {fld[0] + cl[0], fld[1] + cl[1], fld[2] + cl[2]};
    float ta[3] = {fad[0] + ca[0], fad[1] + ca[1], fad[2] + ca[2]};

    float axc = (K == 2) ? ta[2] : ta[1];
    float tau = (NEG ? -axc : axc) + P.damping * qdv;

    float h[3], nl[3], na[3], cx[3];
    rotF<K>(s, ci, tl, h);  mv(P.Rf, h, nl);
    rotF<K>(s, ci, ta, h);  mv(P.Rf, h, na);
    cross3(P.p, nl, cx);
    cl[0] = nl[0]; cl[1] = nl[1]; cl[2] = nl[2];
    ca[0] = na[0] + cx[0]; ca[1] = na[1] + cx[1]; ca[2] = na[2] + cx[2];
    return tau;
}

__global__ void __launch_bounds__(TPB, 4)
rnea_kernel(const float* __restrict__ q,
            const float* __restrict__ qd,
            const float* __restrict__ qdd,
            float* __restrict__ out, int B) {
    __shared__ float sq[TPB*NDOF], sqd[TPB*NDOF], sqdd[TPB*NDOF];
    const int t = threadIdx.x;
    const long base = (long)blockIdx.x * (TPB * NDOF);
    const long total = (long)B * NDOF;

#pragma unroll
    for (int i = 0; i < NDOF; i++) {
        int idx = i * TPB + t;
        long g = base + idx;
        float a = 0.f, bb = 0.f, c = 0.f;
        if (g < total) { a = q[g]; bb = qd[g]; c = qdd[g]; }
        sq[idx] = a; sqd[idx] = bb; sqdd[idx] = c;
    }
    __syncthreads();

    float fl[NDOF][3], fa[NDOF][3];

    float vl[3] = {0.f, 0.f, 0.f};
    float va[3] = {0.f, 0.f, 0.f};
    float al[3] = {0.f, 0.f, GRAV};
    float aa[3] = {0.f, 0.f, 0.f};

    const float* Q  = sq  + t*NDOF;
    const float* QD = sqd + t*NDOF;
    const float* QA = sqdd + t*NDOF;

    // joint axes: [z, y, z, -y, z, y, z]
    fwd_step<2,false>(c_par[0], Q[0], QD[0], QA[0], vl, va, al, aa, fl[0], fa[0]);
    fwd_step<1,false>(c_par[1], Q[1], QD[1], QA[1], vl, va, al, aa, fl[1], fa[1]);
    fwd_step<2,false>(c_par[2], Q[2], QD[2], QA[2], vl, va, al, aa, fl[2], fa[2]);
    fwd_step<1,true >(c_par[3], Q[3], QD[3], QA[3], vl, va, al, aa, fl[3], fa[3]);
    fwd_step<2,false>(c_par[4], Q[4], QD[4], QA[4], vl, va, al, aa, fl[4], fa[4]);
    fwd_step<1,false>(c_par[5], Q[5], QD[5], QA[5], vl, va, al, aa, fl[5], fa[5]);
    fwd_step<2,false>(c_par[6], Q[6], QD[6], QA[6], vl, va, al, aa, fl[6], fa[6]);

    float cl[3] = {0.f, 0.f, 0.f};
    float ca[3] = {0.f, 0.f, 0.f};
    float tau6 = bwd_step<2,false>(c_par[6], Q[6], QD[6], fl[6], fa[6], cl, ca);
    float tau5 = bwd_step<1,false>(c_par[5], Q[5], QD[5], fl[5], fa[5], cl, ca);
    float tau4 = bwd_step<2,false>(c_par[4], Q[4], QD[4], fl[4], fa[4], cl, ca);
    float tau3 = bwd_step<1,true >(c_par[3], Q[3], QD[3], fl[3], fa[3], cl, ca);
    float tau2 = bwd_step<2,false>(c_par[2], Q[2], QD[2], fl[2], fa[2], cl, ca);
    float tau1 = bwd_step<1,false>(c_par[1], Q[1], QD[1], fl[1], fa[1], cl, ca);
    float tau0 = bwd_step<2,false>(c_par[0], Q[0], QD[0], fl[0], fa[0], cl, ca);

    float* TAU = sqdd + t*NDOF;
    TAU[0] = tau0; TAU[1] = tau1; TAU[2] = tau2; TAU[3] = tau3;
    TAU[4] = tau4; TAU[5] = tau5; TAU[6] = tau6;

    __syncthreads();
#pragma unroll
    for (int i = 0; i < NDOF; i++) {
        int idx = i * TPB + t;
        long g = base + idx;
        if (g < total) out[g] = sqdd[idx];
    }
}

extern "C" void kernel_launch(void* const* d_in, const int* in_sizes, int n_in,
                              void* d_out, int out_size) {
    const float* q          = (const float*)d_in[0];
    const float* qd         = (const float*)d_in[1];
    const float* qdd_des    = (const float*)d_in[2];
    const float* rot_fix    = (const float*)d_in[3];
    const float* trans_fix  = (const float*)d_in[4];
    const float* mass       = (const float*)d_in[6];
    const float* com        = (const float*)d_in[7];
    const float* inertia    = (const float*)d_in[8];
    const float* damping    = (const float*)d_in[9];
    float* out = (float*)d_out;

    int B = in_sizes[0] / NDOF;

    prep_kernel<<<1, 32>>>(rot_fix, trans_fix, mass, com, inertia, damping);

    void* src = nullptr;
    cudaGetSymbolAddress(&src, g_stage);
    cudaMemcpyToSymbolAsync(c_par, src, sizeof(JP) * NDOF, 0,
                            cudaMemcpyDeviceToDevice, 0);

    int blocks = (B + TPB - 1) / TPB;
    rnea_kernel<<<blocks, TPB>>>(q, qd, qdd_des, out, B);
}